// round 3
// baseline (speedup 1.0000x reference)
#include <cuda_runtime.h>
#include <cstdint>

// Problem constants (fixed by the reference)
#define NV 65536
#define NB 8
#define FD 16
#define FS 9
#define NUM_ATLAS 100000
#define NUM_SAMPLES (NV * NB)          // 524288
#define ATLAS_STRIDE (FD * FS * FS)    // 1296 floats per atlas entry
#define CH_STRIDE (FS * FS)            // 81 floats per channel

#define NUM_PHASES 8
#define PHASE_SIZE ((NUM_ATLAS + NUM_PHASES - 1) / NUM_PHASES)  // 12500

// One thread per (sample, channel). 16 threads per sample.
// Each launch handles only samples whose ind falls in [lo, hi): this keeps
// the atlas working set (~65 MB) resident in L2 so duplicate inds and
// overlapping sectors are served from L2 instead of DRAM.
__global__ __launch_bounds__(256) void feature_texel_phase_kernel(
    const float2* __restrict__ x,     // [NUM_SAMPLES] (raw x, y in [-1,1])
    const int*    __restrict__ inds,  // [NUM_SAMPLES]
    const float*  __restrict__ ft,    // [NUM_ATLAS * 1296]
    float*        __restrict__ out,   // [NUM_SAMPLES * FD]
    int lo, int hi)
{
    const int gtid   = blockIdx.x * blockDim.x + threadIdx.x;
    const int sample = gtid >> 4;        // /16
    const int c      = gtid & 15;        // channel

    if (sample >= NUM_SAMPLES) return;

    // Broadcast read across the 16 lanes of a sample.
    const int ind = __ldg(&inds[sample]);
    if (ind < lo || ind >= hi) return;   // not this phase

    const float2 xy = __ldg(&x[sample]);

    // Grid coords, matching the reference exactly.
    float gx = (xy.x + 1.0f) * 0.5f * (float)(FS - 1);
    float gy = (xy.y + 1.0f) * 0.5f * (float)(FS - 1);
    gx = fminf(fmaxf(gx, 0.0f), (float)(FS - 1));
    gy = fminf(fmaxf(gy, 0.0f), (float)(FS - 1));

    const float x0f = floorf(gx);
    const float y0f = floorf(gy);
    const float wx  = gx - x0f;
    const float wy  = gy - y0f;

    const int x0 = (int)x0f;
    const int y0 = (int)y0f;
    const int x1 = min(x0 + 1, FS - 1);
    const int y1 = min(y0 + 1, FS - 1);

    const float* __restrict__ tile =
        ft + ((size_t)ind * ATLAS_STRIDE + (size_t)c * CH_STRIDE);

    const int o00 = y0 * FS + x0;
    const int o01 = y0 * FS + x1;
    const int o10 = y1 * FS + x0;
    const int o11 = y1 * FS + x1;

    // 4 independent gathers -> MLP=4 per thread.
    const float v00 = __ldg(tile + o00);
    const float v01 = __ldg(tile + o01);
    const float v10 = __ldg(tile + o10);
    const float v11 = __ldg(tile + o11);

    const float top = v00 * (1.0f - wx) + v01 * wx;
    const float bot = v10 * (1.0f - wx) + v11 * wx;
    const float res = top * (1.0f - wy) + bot * wy;

    // Coalesced: 16 consecutive floats per sample (one 64B chunk).
    out[(size_t)sample * FD + c] = res;
}

extern "C" void kernel_launch(void* const* d_in, const int* in_sizes, int n_in,
                              void* d_out, int out_size)
{
    const float2* x    = (const float2*)d_in[0]; // (NV, NB, 2) f32
    const int*    inds = (const int*)d_in[1];    // (NV, NB) i32
    const float*  ft   = (const float*)d_in[2];  // (NUM_ATLAS, 16, 9, 9) f32
    float*        out  = (float*)d_out;          // (NV, NB, 16) f32

    const int total_threads = NUM_SAMPLES * FD;  // 8,388,608
    const int block = 256;
    const int grid  = (total_threads + block - 1) / block;

    // Sequential phases over ind-ranges; implicit stream ordering keeps each
    // phase's 65 MB atlas slice L2-resident while its samples are processed.
    for (int p = 0; p < NUM_PHASES; ++p) {
        const int lo = p * PHASE_SIZE;
        const int hi = (p + 1 == NUM_PHASES) ? NUM_ATLAS : (lo + PHASE_SIZE);
        feature_texel_phase_kernel<<<grid, block>>>(x, inds, ft, out, lo, hi);
    }
}

// round 4
// speedup vs baseline: 1.6415x; 1.6415x over previous
#include <cuda_runtime.h>
#include <cstdint>

// Problem constants (fixed by the reference)
#define NV 65536
#define NB 8
#define FD 16
#define FS 9
#define NUM_ATLAS 100000
#define NUM_SAMPLES (NV * NB)          // 524288
#define ATLAS_STRIDE (FD * FS * FS)    // 1296 floats per atlas entry
#define CH_STRIDE (FS * FS)            // 81 floats per channel

#define NUM_PHASES 8
#define PHASE_SIZE ((NUM_ATLAS + NUM_PHASES - 1) / NUM_PHASES)  // 12500
// Expected samples/phase = 65536 (sigma ~240). 98304 is >130 sigma of slack.
#define BUCKET_CAP 98304

// Scratch (device globals: allocation-free per harness rules)
__device__ int g_count[NUM_PHASES];
__device__ int g_bucket[NUM_PHASES][BUCKET_CAP];

__global__ void zero_counters_kernel() {
    if (threadIdx.x < NUM_PHASES) g_count[threadIdx.x] = 0;
}

// One thread per sample: bin sample ids by ind-range with warp-aggregated atomics.
__global__ __launch_bounds__(256) void compact_kernel(const int* __restrict__ inds)
{
    const int s = blockIdx.x * blockDim.x + threadIdx.x;  // NUM_SAMPLES % 256 == 0
    const int ind = __ldg(&inds[s]);
    int p = ind / PHASE_SIZE;
    if (p >= NUM_PHASES) p = NUM_PHASES - 1;

    const unsigned mask  = __match_any_sync(0xffffffffu, p);
    const int lane       = threadIdx.x & 31;
    const int leader     = __ffs(mask) - 1;
    int base = 0;
    if (lane == leader) base = atomicAdd(&g_count[p], __popc(mask));
    base = __shfl_sync(mask, base, leader);
    const int pos = base + __popc(mask & ((1u << lane) - 1u));
    if (pos < BUCKET_CAP) g_bucket[p][pos] = s;
}

// Dense phase kernel: 16 threads per bucketed sample, every lane gathers.
// Phase working set = 12500 * 5184 B ~= 65 MB -> L2-resident.
__global__ __launch_bounds__(256) void feature_texel_phase_kernel(
    const float2* __restrict__ x,     // [NUM_SAMPLES]
    const int*    __restrict__ inds,  // [NUM_SAMPLES]
    const float*  __restrict__ ft,    // [NUM_ATLAS * 1296]
    float*        __restrict__ out,   // [NUM_SAMPLES * FD]
    int p)
{
    const int t = blockIdx.x * blockDim.x + threadIdx.x;
    const int i = t >> 4;            // position in bucket
    const int c = t & 15;            // channel

    int cnt = g_count[p];
    if (cnt > BUCKET_CAP) cnt = BUCKET_CAP;
    if (i >= cnt) return;

    const int sample = g_bucket[p][i];          // broadcast across 16 lanes
    const int ind    = __ldg(&inds[sample]);    // broadcast
    const float2 xy  = __ldg(&x[sample]);       // broadcast

    float gx = (xy.x + 1.0f) * 0.5f * (float)(FS - 1);
    float gy = (xy.y + 1.0f) * 0.5f * (float)(FS - 1);
    gx = fminf(fmaxf(gx, 0.0f), (float)(FS - 1));
    gy = fminf(fmaxf(gy, 0.0f), (float)(FS - 1));

    const float x0f = floorf(gx);
    const float y0f = floorf(gy);
    const float wx  = gx - x0f;
    const float wy  = gy - y0f;

    const int x0 = (int)x0f;
    const int y0 = (int)y0f;
    const int x1 = min(x0 + 1, FS - 1);
    const int y1 = min(y0 + 1, FS - 1);

    const float* __restrict__ tile =
        ft + ((size_t)ind * ATLAS_STRIDE + (size_t)c * CH_STRIDE);

    const int o00 = y0 * FS + x0;
    const int o01 = y0 * FS + x1;
    const int o10 = y1 * FS + x0;
    const int o11 = y1 * FS + x1;

    // 4 independent gathers, all lanes active -> full MLP, mostly L2 hits.
    const float v00 = __ldg(tile + o00);
    const float v01 = __ldg(tile + o01);
    const float v10 = __ldg(tile + o10);
    const float v11 = __ldg(tile + o11);

    const float top = v00 * (1.0f - wx) + v01 * wx;
    const float bot = v10 * (1.0f - wx) + v11 * wx;
    const float res = top * (1.0f - wy) + bot * wy;

    out[(size_t)sample * FD + c] = res;       // coalesced 64B per sample
}

extern "C" void kernel_launch(void* const* d_in, const int* in_sizes, int n_in,
                              void* d_out, int out_size)
{
    const float2* x    = (const float2*)d_in[0]; // (NV, NB, 2) f32
    const int*    inds = (const int*)d_in[1];    // (NV, NB) i32
    const float*  ft   = (const float*)d_in[2];  // (NUM_ATLAS, 16, 9, 9) f32
    float*        out  = (float*)d_out;          // (NV, NB, 16) f32

    zero_counters_kernel<<<1, 32>>>();

    compact_kernel<<<NUM_SAMPLES / 256, 256>>>(inds);

    const int phase_grid = (BUCKET_CAP * FD) / 256;  // 6144 blocks
    for (int p = 0; p < NUM_PHASES; ++p) {
        feature_texel_phase_kernel<<<phase_grid, 256>>>(x, inds, ft, out, p);
    }
}

// round 5
// speedup vs baseline: 1.7633x; 1.0742x over previous
#include <cuda_runtime.h>
#include <cstdint>

// Problem constants (fixed by the reference)
#define NV 65536
#define NB 8
#define FD 16
#define FS 9
#define NUM_ATLAS 100000
#define NUM_SAMPLES (NV * NB)          // 524288
#define ATLAS_STRIDE (FD * FS * FS)    // 1296 floats per atlas entry
#define CH_STRIDE (FS * FS)            // 81 floats per channel

#define NUM_PHASES 8
#define PHASE_SIZE ((NUM_ATLAS + NUM_PHASES - 1) / NUM_PHASES)  // 12500
// Expected samples/phase = 65536 (sigma ~240). 98304 is huge slack.
#define BUCKET_CAP 98304

// Scratch (device globals: allocation-free per harness rules)
__device__ int  g_count[NUM_PHASES];
__device__ int4 g_bucket[NUM_PHASES][BUCKET_CAP];  // {sample, ind|x0<<17|y0<<21, wx, wy}

__global__ void zero_counters_kernel() {
    if (threadIdx.x < NUM_PHASES) g_count[threadIdx.x] = 0;
}

// One thread per sample: precompute sampling params and bin into dense
// per-phase buckets with warp-aggregated atomics.
__global__ __launch_bounds__(256) void compact_kernel(
    const int*    __restrict__ inds,
    const float2* __restrict__ x)
{
    const int s = blockIdx.x * blockDim.x + threadIdx.x;  // NUM_SAMPLES % 256 == 0
    const int ind = __ldg(&inds[s]);
    const float2 xy = __ldg(&x[s]);

    float gx = (xy.x + 1.0f) * 0.5f * (float)(FS - 1);
    float gy = (xy.y + 1.0f) * 0.5f * (float)(FS - 1);
    gx = fminf(fmaxf(gx, 0.0f), (float)(FS - 1));
    gy = fminf(fmaxf(gy, 0.0f), (float)(FS - 1));
    const float x0f = floorf(gx);
    const float y0f = floorf(gy);
    const float wx  = gx - x0f;
    const float wy  = gy - y0f;
    const int x0 = (int)x0f;
    const int y0 = (int)y0f;

    int p = ind / PHASE_SIZE;
    if (p >= NUM_PHASES) p = NUM_PHASES - 1;

    const unsigned mask  = __match_any_sync(0xffffffffu, p);
    const int lane       = threadIdx.x & 31;
    const int leader     = __ffs(mask) - 1;
    int base = 0;
    if (lane == leader) base = atomicAdd(&g_count[p], __popc(mask));
    base = __shfl_sync(mask, base, leader);
    const int pos = base + __popc(mask & ((1u << lane) - 1u));

    if (pos < BUCKET_CAP) {
        int4 rec;
        rec.x = s;
        rec.y = ind | (x0 << 17) | (y0 << 21);   // ind<2^17, x0/y0 in [0,8]
        rec.z = __float_as_int(wx);
        rec.w = __float_as_int(wy);
        g_bucket[p][pos] = rec;
    }
}

// Decode one record and compute the bilinear sample for channel c.
__device__ __forceinline__ void gather_one(
    const float* __restrict__ ft, float* __restrict__ out,
    const int4 rec, const int c)
{
    const int sample = rec.x;
    const int ind    = rec.y & 0x1FFFF;
    const int x0     = (rec.y >> 17) & 0xF;
    const int y0     = (rec.y >> 21) & 0xF;
    const float wx   = __int_as_float(rec.z);
    const float wy   = __int_as_float(rec.w);
    const int x1 = min(x0 + 1, FS - 1);
    const int y1 = min(y0 + 1, FS - 1);

    const float* __restrict__ tile =
        ft + ((size_t)ind * ATLAS_STRIDE + (size_t)c * CH_STRIDE);

    const float v00 = __ldg(tile + y0 * FS + x0);
    const float v01 = __ldg(tile + y0 * FS + x1);
    const float v10 = __ldg(tile + y1 * FS + x0);
    const float v11 = __ldg(tile + y1 * FS + x1);

    const float top = v00 * (1.0f - wx) + v01 * wx;
    const float bot = v10 * (1.0f - wx) + v11 * wx;
    out[(size_t)sample * FD + c] = top * (1.0f - wy) + bot * wy;
}

// Dense phase kernel: 16 threads per sample, 2 samples per thread.
// Single broadcast 16B record load, then 8 independent gathers (MLP=8).
__global__ __launch_bounds__(256) void feature_texel_phase_kernel(
    const float* __restrict__ ft,
    float*       __restrict__ out,
    int p)
{
    const int t = blockIdx.x * blockDim.x + threadIdx.x;
    const int i = t >> 4;            // position in first half of bucket
    const int c = t & 15;            // channel

    int cnt = g_count[p];
    if (cnt > BUCKET_CAP) cnt = BUCKET_CAP;
    const int half = (cnt + 1) >> 1;
    if (i >= half) return;

    const int4* bkt = &g_bucket[p][0];
    const int4 rec0 = __ldg(bkt + i);
    const bool has1 = (i + half) < cnt;
    const int4 rec1 = has1 ? __ldg(bkt + i + half) : rec0;

    // Issue both samples' gathers; independent loads get front-batched.
    gather_one(ft, out, rec0, c);
    if (has1) gather_one(ft, out, rec1, c);
}

extern "C" void kernel_launch(void* const* d_in, const int* in_sizes, int n_in,
                              void* d_out, int out_size)
{
    const float2* x    = (const float2*)d_in[0]; // (NV, NB, 2) f32
    const int*    inds = (const int*)d_in[1];    // (NV, NB) i32
    const float*  ft   = (const float*)d_in[2];  // (NUM_ATLAS, 16, 9, 9) f32
    float*        out  = (float*)d_out;          // (NV, NB, 16) f32

    zero_counters_kernel<<<1, 32>>>();
    compact_kernel<<<NUM_SAMPLES / 256, 256>>>(inds, x);

    // Threads per phase: (BUCKET_CAP/2) pairs * 16 channels.
    const int phase_grid = (BUCKET_CAP / 2 * FD) / 256;  // 3072 blocks
    for (int p = 0; p < NUM_PHASES; ++p) {
        feature_texel_phase_kernel<<<phase_grid, 256>>>(ft, out, p);
    }
}